// round 4
// baseline (speedup 1.0000x reference)
#include <cuda_runtime.h>

// Clifford geometric product in Cl(3,0,0), blade order (grade-lex):
//   0:1, 1:e1, 2:e2, 3:e3, 4:e12, 5:e13, 6:e23, 7:e123
// out = a * b with hardcoded Cayley signs (metric = +1,+1,+1).
// Pure streaming kernel: one thread per multivector (8 floats), float4 I/O.

__global__ void __launch_bounds__(256) clifford_gp_kernel(
    const float4* __restrict__ a4,
    const float4* __restrict__ b4,
    float4* __restrict__ o4,
    int n_mv)
{
    int t = blockIdx.x * blockDim.x + threadIdx.x;
    if (t >= n_mv) return;

    const float4 al = a4[2 * t];
    const float4 ah = a4[2 * t + 1];
    const float4 bl = b4[2 * t];
    const float4 bh = b4[2 * t + 1];

    const float a0 = al.x, a1 = al.y, a2 = al.z, a3 = al.w;
    const float a4_ = ah.x, a5 = ah.y, a6 = ah.z, a7 = ah.w;
    const float b0 = bl.x, b1 = bl.y, b2 = bl.z, b3 = bl.w;
    const float b4_ = bh.x, b5 = bh.y, b6 = bh.z, b7 = bh.w;

    // out0 (scalar)
    float o0 = a0*b0 + a1*b1 + a2*b2 + a3*b3 - a4_*b4_ - a5*b5 - a6*b6 - a7*b7;
    // out1 (e1)
    float o1 = a0*b1 + a1*b0 - a2*b4_ - a3*b5 + a4_*b2 + a5*b3 - a6*b7 - a7*b6;
    // out2 (e2)
    float o2 = a0*b2 + a1*b4_ + a2*b0 - a3*b6 - a4_*b1 + a5*b7 + a6*b3 + a7*b5;
    // out3 (e3)
    float o3 = a0*b3 + a1*b5 + a2*b6 + a3*b0 - a4_*b7 - a5*b1 - a6*b2 - a7*b4_;
    // out4 (e12)
    float o4v = a0*b4_ + a1*b2 - a2*b1 + a3*b7 + a4_*b0 - a5*b6 + a6*b5 + a7*b3;
    // out5 (e13)
    float o5 = a0*b5 + a1*b3 - a2*b7 - a3*b1 + a4_*b6 + a5*b0 - a6*b4_ - a7*b2;
    // out6 (e23)
    float o6 = a0*b6 + a1*b7 + a2*b3 - a3*b2 - a4_*b5 + a5*b4_ + a6*b0 + a7*b1;
    // out7 (e123)
    float o7 = a0*b7 + a1*b6 - a2*b5 + a3*b4_ + a4_*b3 - a5*b2 + a6*b1 + a7*b0;

    o4[2 * t]     = make_float4(o0, o1, o2, o3);
    o4[2 * t + 1] = make_float4(o4v, o5, o6, o7);
}

extern "C" void kernel_launch(void* const* d_in, const int* in_sizes, int n_in,
                              void* d_out, int out_size)
{
    const float4* a4 = (const float4*)d_in[0];
    const float4* b4 = (const float4*)d_in[1];
    // d_in[2] = cayley[8,8,8] — deterministic for METRIC=(1,1,1); signs are baked in.
    float4* o4 = (float4*)d_out;

    int n_mv = in_sizes[0] / 8;  // number of multivectors
    int threads = 256;
    int blocks = (n_mv + threads - 1) / threads;
    clifford_gp_kernel<<<blocks, threads>>>(a4, b4, o4, n_mv);
}